// round 9
// baseline (speedup 1.0000x reference)
#include <cuda_runtime.h>
#include <cuda_bf16.h>
#include <cstddef>

// WKV2D: B=8, H=16, W=16, C=256.
// k_adj = sum_taps relu(k - w[c]*manhattan_d) (+u bonus at center); out = exp(k_adj)*v.
// Sparsity: taps with d > r = floor(kmax_c/w_c)+1 are exactly zero (w>0).
// Halo trick: -1e30 padding => relu gives exact 0, no bounds checks in fast path.
//
// Block = 8 consecutive channels x whole 16x16 image of one batch; 256 threads.
// Thread (c = t&7, s = t>>3) owns 8 horizontally-consecutive pixels of one
// channel -> every global access is a fully-utilized 32B sector.

#define B_DIM   8
#define C_DIM   256
#define CCH     8
#define PAD     2            // fast path covers r <= 2 (r>=3 falls back, ~never)
#define TW      20           // padded row stride (16 + 2*PAD)
#define CPLANE  405          // 400 used; 405 % 32 == 21 -> near-conflict-free

__device__ __forceinline__ float relu_(float x) { return fmaxf(x, 0.0f); }

// 8 consecutive pixels of one channel, compile-time radius.
// Center tap (0,0) EXCLUDED (handled by the u-bonus init).
// ALL tap segments are loaded in one MLP burst before any FP math:
// one deep LDS stall instead of 2R+1 shallow ones.
template<int R>
__device__ __forceinline__ void diamond8(const float* __restrict__ ksb, int pos0,
                                         float wneg, float acc[8])
{
    float wd[2 * R + 1];
    #pragma unroll
    for (int d = 0; d <= 2 * R; ++d) wd[d] = wneg * (float)d;

    // ---- phase 1: issue every LDS up front (independent, deep MLP) ----
    float seg[2 * R + 1][8 + 2 * R];
    #pragma unroll
    for (int di = -R; di <= R; ++di) {
        const int adi = di < 0 ? -di : di;
        const int rr  = R - adi;
        const int sbase = pos0 + di * TW - rr;
        #pragma unroll
        for (int j = 0; j < 8 + 2 * rr; ++j)
            seg[di + R][j] = ksb[sbase + j];
    }

    // ---- phase 2: pure FP, 8 independent accumulator chains ----
    #pragma unroll
    for (int di = -R; di <= R; ++di) {
        const int adi = di < 0 ? -di : di;
        const int rr  = R - adi;
        #pragma unroll
        for (int i = 0; i < 8; ++i) {
            #pragma unroll
            for (int dj = -rr; dj <= rr; ++dj) {
                if (di == 0 && dj == 0) continue;   // center handled in init
                const int adj = dj < 0 ? -dj : dj;
                acc[i] += relu_(seg[di + R][i + dj + rr] + wd[adi + adj]);
            }
        }
    }
}

__global__ __launch_bounds__(256)
void wkv2d_kernel(const float* __restrict__ w,
                  const float* __restrict__ u,
                  const float* __restrict__ k,
                  const float* __restrict__ v,
                  float* __restrict__ out)
{
    __shared__ float ks[CCH * CPLANE];              // 8 padded channel planes (~13KB)
    __shared__ __align__(16) float red[CCH * 8];    // [c][warp] partial maxes

    const int b  = blockIdx.x >> 5;      // 32 channel-chunks per batch
    const int c0 = (blockIdx.x & 31) * CCH;
    const int t  = threadIdx.x;
    const int c  = t & 7;
    const int s  = t >> 3;               // 0..31
    const int y  = s >> 1;
    const int x0 = (s & 1) << 3;

    const size_t base = ((size_t)b * 256) * C_DIM + c0;
    const float* kg = k + base + c;
    const float* vg = v + base + c;
    const int px0 = (y << 4) + x0;

    // ---- issue the 8 k loads up front (MLP); v comes after the barrier ----
    float kr[8];
    #pragma unroll
    for (int i = 0; i < 8; ++i) kr[i] = kg[(size_t)(px0 + i) * C_DIM];

    const float wv = w[c0 + c];
    const float uv = u[c0 + c];

    // ---- halo-only fill: 144 halo cells/plane ----
    // rows 0,1,18,19 full (4*20=80); rows 2..17 cols {0,1,18,19} (16*4=64)
    if (t < 144) {
        int row, col;
        if (t < 80) {
            int r4 = t / 20;
            col = t - r4 * 20;
            row = r4 < 2 ? r4 : r4 + 16;
        } else {
            int q = t - 80;
            int qr = q >> 2;
            int ci = q & 3;
            row = 2 + qr;
            col = ci < 2 ? ci : ci + 16;
        }
        const int pos = row * TW + col;
        #pragma unroll
        for (int p = 0; p < CCH; ++p)
            ks[p * CPLANE + pos] = -1e30f;
    }

    // ---- interior stores + per-channel partial max (registers) ----
    float* ksb = ks + c * CPLANE;
    const int pos0 = (y + PAD) * TW + (x0 + PAD);
    float m = kr[0];
    #pragma unroll
    for (int i = 0; i < 8; ++i) {
        ksb[pos0 + i] = kr[i];
        if (i) m = fmaxf(m, kr[i]);
    }
    // reduce over lanes with the same channel (xor 8, 16)
    m = fmaxf(m, __shfl_xor_sync(0xffffffffu, m, 8));
    m = fmaxf(m, __shfl_xor_sync(0xffffffffu, m, 16));
    if ((t & 31) < 8) red[c * 8 + (t >> 5)] = m;

    __syncthreads();   // single barrier: tile + halo + red all visible

    // ---- v loads now: in flight during r-compute + diamond ----
    float vr[8];
    #pragma unroll
    for (int i = 0; i < 8; ++i) vr[i] = vg[(size_t)(px0 + i) * C_DIM];

    const float4 ra = *(const float4*)&red[c * 8];
    const float4 rb = *(const float4*)&red[c * 8 + 4];
    float mm = fmaxf(fmaxf(fmaxf(ra.x, ra.y), fmaxf(ra.z, ra.w)),
                     fmaxf(fmaxf(rb.x, rb.y), fmaxf(rb.z, rb.w)));

    int rch = (int)__fdividef(fmaxf(mm, 0.0f), wv) + 1;  // taps with d > rch exactly 0
    rch = min(rch, 30);
    const int r = __reduce_max_sync(0xffffffffu, rch);   // warp holds all 8 c -> block max

    const float wneg = -wv;

    // ---- init acc with the center term: relu(k + u) ----
    float acc[8];
    #pragma unroll
    for (int i = 0; i < 8; ++i)
        acc[i] = relu_(kr[i] + uv);

    if (r <= PAD) {
        if (r == 1) diamond8<1>(ksb, pos0, wneg, acc);
        else        diamond8<2>(ksb, pos0, wneg, acc);
    } else {
        // generic bounds-checked fallback (essentially never taken);
        // reads only the 16x16 interior of the tile, never the halo.
        #pragma unroll
        for (int i = 0; i < 8; ++i) {
            const int xx = x0 + i;
            float a = acc[i];
            for (int di = -r; di <= r; ++di) {
                int iy = y + di;
                if ((unsigned)iy >= 16u) continue;
                int adi = di < 0 ? -di : di;
                int rr = r - adi;
                for (int dj = -rr; dj <= rr; ++dj) {
                    if (di == 0 && dj == 0) continue;
                    int ix = xx + dj;
                    if ((unsigned)ix >= 16u) continue;
                    int adj_ = dj < 0 ? -dj : dj;
                    a += relu_(fmaf(wneg, (float)(adi + adj_),
                                    ksb[(iy + PAD) * TW + ix + PAD]));
                }
            }
            acc[i] = a;
        }
    }

    // ---- epilogue: fully-sectored stores ----
    float* og = out + base + c;
    #pragma unroll
    for (int i = 0; i < 8; ++i)
        og[(size_t)(px0 + i) * C_DIM] = __expf(acc[i]) * vr[i];
}

extern "C" void kernel_launch(void* const* d_in, const int* in_sizes, int n_in,
                              void* d_out, int out_size)
{
    const float *w = nullptr, *u = nullptr, *k = nullptr, *v = nullptr;
    for (int i = 0; i < n_in; i++) {
        if (in_sizes[i] == C_DIM) {
            if (!w) w = (const float*)d_in[i];
            else if (!u) u = (const float*)d_in[i];
        } else if (in_sizes[i] == B_DIM * 256 * C_DIM) {
            if (!k) k = (const float*)d_in[i];
            else if (!v) v = (const float*)d_in[i];
        }
    }
    wkv2d_kernel<<<B_DIM * (C_DIM / CCH), 256>>>(w, u, k, v, (float*)d_out);
}